// round 14
// baseline (speedup 1.0000x reference)
#include <cuda_runtime.h>
#include <cuda_fp16.h>

// ---------------------------------------------------------------------------
// AggNet: 4x ChebConv(K=3) + node MLP + 2x edge MLP, N=200K, E=3.2M.
// R14: R12/13 + (a) final F=1 SPMM (t=spmm(s)) fused into k_nodemlp (one
// fewer launch, gather hidden under MLP FMAs), (b) 4-edges-per-thread k_edge.
// ---------------------------------------------------------------------------

static constexpr int NMAX = 200000;
static constexpr int EMAX = 3200000;

// -------- static device scratch ---------------------------------------------
__device__ int2  g_edge[EMAX];      // (row, wn-bits) sorted by col
__device__ int   g_off[NMAX + 1];
__device__ int   g_cursor[NMAX];
__device__ int   g_cnt[NMAX];
__device__ float g_deg[NMAX];
__device__ float g_rdis[NMAX];
__device__ int   g_part[1024];

__device__ float g_x1[NMAX * 4];
__device__ float g_x2[NMAX * 16];
__device__ float g_x3[NMAX * 64];
__device__ float g_tx1[NMAX * 16];  // fp32 Tx1 scratch (layers 1,2)
__device__ float g_s2f[NMAX * 16];  // fp32 spmm(Tx1) for layer 3 combine
__device__ __align__(16) __half g_xn3[NMAX * 16];  // normalized x2, fp16
__device__ __align__(16) __half g_th3[NMAX * 16];  // Tx1 (layer3), fp16
__device__ float g_u[NMAX];
__device__ float g_qr[NMAX * 2];    // (q, r) interleaved
__device__ float g_tqs[NMAX * 2];   // (Tq, s) interleaved
__device__ float g_sums[192];       // su1@0(2) su2@2(8) su3@10(32) su4@42(128)

// ---------------------------------------------------------------------------
__global__ void k_zero(int N) {
    int i = blockIdx.x * blockDim.x + threadIdx.x;
    if (i < N) { g_cnt[i] = 0; g_deg[i] = 0.f; }
    if (i < 192) g_sums[i] = 0.f;
}

__global__ void k_count(const int* __restrict__ ei, const float* __restrict__ ea, int E) {
    int e0 = (blockIdx.x * blockDim.x + threadIdx.x) * 2;
    if (e0 >= E) return;
    if (e0 + 1 < E) {
        int2 rr = *reinterpret_cast<const int2*>(ei + e0);
        int2 cc = *reinterpret_cast<const int2*>(ei + E + e0);
        float2 aa = *reinterpret_cast<const float2*>(ea + e0);
        atomicAdd(&g_cnt[cc.x], 1);
        atomicAdd(&g_cnt[cc.y], 1);
        atomicAdd(&g_deg[rr.x], aa.x);
        atomicAdd(&g_deg[rr.y], aa.y);
    } else {
        atomicAdd(&g_cnt[ei[E + e0]], 1);
        atomicAdd(&g_deg[ei[e0]], ea[e0]);
    }
}

// ---- scanA: per-512-tile local exclusive + tile aggregates ------------------
__global__ void k_scanA(int n) {
    __shared__ int sd[512];
    int i = blockIdx.x * 512 + threadIdx.x;
    int v = (i < n) ? g_cnt[i] : 0;
    sd[threadIdx.x] = v;
    __syncthreads();
    for (int s = 1; s < 512; s <<= 1) {
        int t = (threadIdx.x >= s) ? sd[threadIdx.x - s] : 0;
        __syncthreads();
        sd[threadIdx.x] += t;
        __syncthreads();
    }
    if (i < n) g_off[i] = sd[threadIdx.x] - v;
    if (threadIdx.x == 511) g_part[blockIdx.x] = sd[511];
}

// ---- scanC: tile prefix (per-block sum of g_part), offsets, rdis, su1 ------
__global__ void k_scanC(const float* __restrict__ x, int n, int e, float* __restrict__ su1) {
    __shared__ int pr[256];
    __shared__ float ss[2];
    int tid = threadIdx.x;
    if (tid < 2) ss[tid] = 0.f;

    int t0 = blockIdx.x >> 1;       // 512-wide scanA tile containing this block
    int part = 0;
    for (int j = tid; j < t0; j += 256) part += g_part[j];
    pr[tid] = part;
    __syncthreads();
    for (int s = 128; s; s >>= 1) {
        if (tid < s) pr[tid] += pr[tid + s];
        __syncthreads();
    }
    int pre = pr[0];

    int i = blockIdx.x * 256 + tid;
    float v = 0.f;
    if (i < n) {
        int o = g_off[i] + pre;
        g_off[i] = o;
        g_cursor[i] = o;
        float d = g_deg[i];
        g_rdis[i] = (d > 0.f) ? rsqrtf(d) : 0.f;
        v = x[i];
    }
    if (i == 0) g_off[n] = e;
    float s = v, s2 = v * v;
#pragma unroll
    for (int m = 16; m; m >>= 1) {
        s  += __shfl_xor_sync(0xffffffffu, s, m);
        s2 += __shfl_xor_sync(0xffffffffu, s2, m);
    }
    if ((tid & 31) == 0) { atomicAdd(&ss[0], s); atomicAdd(&ss[1], s2); }
    __syncthreads();
    if (tid == 0) { atomicAdd(&su1[0], ss[0]); atomicAdd(&su1[1], ss[1]); }
}

__global__ void k_scatter(const int* __restrict__ ei, const float* __restrict__ ea, int E) {
    int e0 = (blockIdx.x * blockDim.x + threadIdx.x) * 2;
    if (e0 >= E) return;
    if (e0 + 1 < E) {
        int2 rr = *reinterpret_cast<const int2*>(ei + e0);
        int2 cc = *reinterpret_cast<const int2*>(ei + E + e0);
        float2 aa = *reinterpret_cast<const float2*>(ea + e0);
        int p0 = atomicAdd(&g_cursor[cc.x], 1);
        g_edge[p0] = make_int2(rr.x, __float_as_int(-g_rdis[rr.x] * aa.x * g_rdis[cc.x]));
        int p1 = atomicAdd(&g_cursor[cc.y], 1);
        g_edge[p1] = make_int2(rr.y, __float_as_int(-g_rdis[rr.y] * aa.y * g_rdis[cc.y]));
    } else {
        int r = ei[e0];
        int c = ei[E + e0];
        int p = atomicAdd(&g_cursor[c], 1);
        g_edge[p] = make_int2(r, __float_as_int(-g_rdis[r] * ea[e0] * g_rdis[c]));
    }
}

// ---- raw-sum reduction for layer-4 stats (x3, F=64) ------------------------
template<int F>
__global__ void k_reduce(const float* __restrict__ x, float* __restrict__ sums, int N) {
    constexpr int G = 256 / F;
    int f = threadIdx.x & (F - 1);
    int g = threadIdx.x / F;
    float s = 0.f, s2 = 0.f;
    for (int n = blockIdx.x * G + g; n < N; n += gridDim.x * G) {
        float v = x[n * F + f];
        s += v;
        s2 += v * v;
    }
    __shared__ float rs[256], rq[256];
    rs[threadIdx.x] = s;
    rq[threadIdx.x] = s2;
    __syncthreads();
    for (int step = 128; step >= F; step >>= 1) {
        if ((int)threadIdx.x < step) {
            rs[threadIdx.x] += rs[threadIdx.x + step];
            rq[threadIdx.x] += rq[threadIdx.x + step];
        }
        __syncthreads();
    }
    if ((int)threadIdx.x < F) {
        atomicAdd(&sums[f], rs[f]);
        atomicAdd(&sums[F + f], rq[f]);
    }
}

// ---- vector load helper ----------------------------------------------------
template<int VEC>
__device__ __forceinline__ void loadvec(float* v, const float* p) {
    if (VEC == 4) {
        float4 t = *reinterpret_cast<const float4*>(p);
        v[0] = t.x; v[1] = t.y; v[2] = t.z; v[3] = t.w;
    } else if (VEC == 2) {
        float2 t = *reinterpret_cast<const float2*>(p);
        v[0] = t.x; v[1] = t.y;
    } else {
        v[0] = *p;
    }
}

// ---- generic vectorized SPMM; NORM computes stats from raw sums ------------
template<int F, int VEC, int GROUP, bool NORM>
__global__ void k_spmm(const float* __restrict__ z, const float* __restrict__ sums,
                       float* __restrict__ out, int N, int zs, int os) {
    constexpr int LPE = F / VEC;
    constexpr int EPI = GROUP / LPE;
    constexpr int NPW = 32 / GROUP;

    int lane = threadIdx.x & 31;
    int wid  = (blockIdx.x * blockDim.x + threadIdx.x) >> 5;
    int sub  = lane / GROUP;
    int gl   = lane % GROUP;
    int eg   = gl / LPE;
    int fl   = gl % LPE;

    int node = wid * NPW + sub;

    float m[VEC], rv[VEC];
#pragma unroll
    for (int i = 0; i < VEC; i++) { m[i] = 0.f; rv[i] = 1.f; }
    if (NORM) {
        float invn = 1.f / (float)N;
#pragma unroll
        for (int i = 0; i < VEC; i++) {
            int f = fl * VEC + i;
            float mm = sums[f] * invn;
            float var = sums[F + f] * invn - mm * mm;
            if (var < 0.f) var = 0.f;
            m[i] = mm;
            rv[i] = rsqrtf(var + 1e-5f);
        }
    }

    int e0 = 0, e1 = 0;
    if (node < N) { e0 = g_off[node]; e1 = g_off[node + 1]; }

    float acc[VEC];
#pragma unroll
    for (int i = 0; i < VEC; i++) acc[i] = 0.f;

    int e = e0 + eg;
    for (; e + EPI < e1; e += 2 * EPI) {
        int2 ed0 = g_edge[e];
        int2 ed1 = g_edge[e + EPI];
        float w0 = __int_as_float(ed0.y);
        float w1 = __int_as_float(ed1.y);
        float v0[VEC], v1[VEC];
        loadvec<VEC>(v0, z + (size_t)ed0.x * zs + fl * VEC);
        loadvec<VEC>(v1, z + (size_t)ed1.x * zs + fl * VEC);
#pragma unroll
        for (int i = 0; i < VEC; i++) {
            float a = NORM ? (v0[i] - m[i]) * rv[i] : v0[i];
            float b = NORM ? (v1[i] - m[i]) * rv[i] : v1[i];
            acc[i] = fmaf(w0, a, acc[i]);
            acc[i] = fmaf(w1, b, acc[i]);
        }
    }
    if (e < e1) {
        int2 ed = g_edge[e];
        float w = __int_as_float(ed.y);
        float v[VEC];
        loadvec<VEC>(v, z + (size_t)ed.x * zs + fl * VEC);
#pragma unroll
        for (int i = 0; i < VEC; i++) {
            float a = NORM ? (v[i] - m[i]) * rv[i] : v[i];
            acc[i] = fmaf(w, a, acc[i]);
        }
    }

#pragma unroll
    for (int s = LPE; s < GROUP; s <<= 1) {
#pragma unroll
        for (int i = 0; i < VEC; i++)
            acc[i] += __shfl_xor_sync(0xffffffffu, acc[i], s);
    }

    if (node < N && eg == 0) {
        float* op = out + (size_t)node * os + fl * VEC;
        if (VEC == 4) {
            *reinterpret_cast<float4*>(op) = make_float4(acc[0], acc[1], acc[2], acc[3]);
        } else if (VEC == 2) {
            *reinterpret_cast<float2*>(op) = make_float2(acc[0], acc[1]);
        } else {
            *op = acc[0];
        }
    }
}

// ---- fused layer-1 pass2 + combine + su2 stats (4 lanes/node, 2-way) -------
__global__ void k_fuse1(const float* __restrict__ x, const float* __restrict__ su1,
                        const float* __restrict__ tx1,
                        const float* __restrict__ W, const float* __restrict__ b,
                        float* __restrict__ x1, float* __restrict__ su2, int N) {
    __shared__ float sw[12], sb[4], ssum[4], ssq[4];
    int tid = threadIdx.x;
    if (tid < 4) {
        sw[tid] = W[tid] - W[8 + tid];
        sw[4 + tid] = W[4 + tid];
        sw[8 + tid] = 2.f * W[8 + tid];
        sb[tid] = b[tid];
        ssum[tid] = 0.f;
        ssq[tid] = 0.f;
    }
    __syncthreads();
    int lane = tid & 31;
    int wid = (blockIdx.x * blockDim.x + tid) >> 5;
    int sub = lane >> 2;        // 8 nodes per warp
    int gl = lane & 3;          // 4 edge slots -> later feature index
    int node = wid * 8 + sub;
    bool valid = node < N;
    int e0 = 0, e1 = 0;
    if (valid) { e0 = g_off[node]; e1 = g_off[node + 1]; }
    float acc = 0.f;
    int e = e0 + gl;
    for (; e + 4 < e1; e += 8) {
        int2 a = g_edge[e];
        int2 b2 = g_edge[e + 4];
        float za = __ldg(&tx1[a.x]);
        float zb = __ldg(&tx1[b2.x]);
        acc = fmaf(__int_as_float(a.y), za, acc);
        acc = fmaf(__int_as_float(b2.y), zb, acc);
    }
    if (e < e1) {
        int2 a = g_edge[e];
        acc = fmaf(__int_as_float(a.y), __ldg(&tx1[a.x]), acc);
    }
    acc += __shfl_xor_sync(0xffffffffu, acc, 1);
    acc += __shfl_xor_sync(0xffffffffu, acc, 2);

    float v = 0.f;
    if (valid) {
        float invn = 1.f / (float)N;
        float mm = su1[0] * invn;
        float var = su1[1] * invn - mm * mm;
        if (var < 0.f) var = 0.f;
        float rv = rsqrtf(var + 1e-5f);
        float xin = (x[node] - mm) * rv;
        float t1 = tx1[node];
        v = fmaxf(fmaf(xin, sw[gl], fmaf(t1, sw[4 + gl], fmaf(acc, sw[8 + gl], sb[gl]))), 0.f);
        x1[(size_t)node * 4 + gl] = v;
    }
    float vq = v * v;
#pragma unroll
    for (int s = 4; s < 32; s <<= 1) {
        v  += __shfl_xor_sync(0xffffffffu, v,  s);
        vq += __shfl_xor_sync(0xffffffffu, vq, s);
    }
    if (lane < 4) {
        atomicAdd(&ssum[gl], v);
        atomicAdd(&ssq[gl], vq);
    }
    __syncthreads();
    if (tid < 4) {
        atomicAdd(&su2[tid], ssum[tid]);
        atomicAdd(&su2[4 + tid], ssq[tid]);
    }
}

// ---- fused layer-2 pass2 + combine + su3 stats (16 lanes/node, 2-way) ------
__global__ void k_fuse2(const float* __restrict__ x1, const float* __restrict__ su2,
                        const float* __restrict__ tx1,
                        const float* __restrict__ W, const float* __restrict__ b,
                        float* __restrict__ x2, float* __restrict__ su3, int N) {
    __shared__ float sw[192], sb[16], sm[4], srv[4], ssum[16], ssq[16];
    int tid = threadIdx.x;
    for (int i = tid; i < 64; i += blockDim.x) {
        sw[i] = W[i] - W[128 + i];
        sw[64 + i] = W[64 + i];
        sw[128 + i] = 2.f * W[128 + i];
    }
    if (tid < 16) { sb[tid] = b[tid]; ssum[tid] = 0.f; ssq[tid] = 0.f; }
    if (tid < 4) {
        float invn = 1.f / (float)N;
        float mm = su2[tid] * invn;
        float var = su2[4 + tid] * invn - mm * mm;
        if (var < 0.f) var = 0.f;
        sm[tid] = mm;
        srv[tid] = rsqrtf(var + 1e-5f);
    }
    __syncthreads();
    int lane = tid & 31;
    int wid = (blockIdx.x * blockDim.x + tid) >> 5;
    int sub = lane >> 4;
    int gl = lane & 15;
    int node = wid * 2 + sub;
    bool valid = node < N;
    int e0 = 0, e1 = 0;
    if (valid) { e0 = g_off[node]; e1 = g_off[node + 1]; }
    float a0 = 0.f, a1 = 0.f, a2 = 0.f, a3 = 0.f;
    int e = e0 + gl;
    for (; e + 16 < e1; e += 32) {
        int2 eda = g_edge[e];
        int2 edb = g_edge[e + 16];
        float wa = __int_as_float(eda.y);
        float wb = __int_as_float(edb.y);
        float4 ta = *reinterpret_cast<const float4*>(tx1 + (size_t)eda.x * 4);
        float4 tb = *reinterpret_cast<const float4*>(tx1 + (size_t)edb.x * 4);
        a0 = fmaf(wa, ta.x, a0); a0 = fmaf(wb, tb.x, a0);
        a1 = fmaf(wa, ta.y, a1); a1 = fmaf(wb, tb.y, a1);
        a2 = fmaf(wa, ta.z, a2); a2 = fmaf(wb, tb.z, a2);
        a3 = fmaf(wa, ta.w, a3); a3 = fmaf(wb, tb.w, a3);
    }
    if (e < e1) {
        int2 eda = g_edge[e];
        float wa = __int_as_float(eda.y);
        float4 ta = *reinterpret_cast<const float4*>(tx1 + (size_t)eda.x * 4);
        a0 = fmaf(wa, ta.x, a0);
        a1 = fmaf(wa, ta.y, a1);
        a2 = fmaf(wa, ta.z, a2);
        a3 = fmaf(wa, ta.w, a3);
    }
#pragma unroll
    for (int s = 1; s < 16; s <<= 1) {
        a0 += __shfl_xor_sync(0xffffffffu, a0, s);
        a1 += __shfl_xor_sync(0xffffffffu, a1, s);
        a2 += __shfl_xor_sync(0xffffffffu, a2, s);
        a3 += __shfl_xor_sync(0xffffffffu, a3, s);
    }
    float v = 0.f;
    if (valid) {
        float4 t1 = *reinterpret_cast<const float4*>(tx1 + (size_t)node * 4);
        float xi0 = (x1[(size_t)node * 4 + 0] - sm[0]) * srv[0];
        float xi1 = (x1[(size_t)node * 4 + 1] - sm[1]) * srv[1];
        float xi2 = (x1[(size_t)node * 4 + 2] - sm[2]) * srv[2];
        float xi3 = (x1[(size_t)node * 4 + 3] - sm[3]) * srv[3];
        float acc = sb[gl];
        acc = fmaf(xi0, sw[gl],      fmaf(t1.x, sw[64 + gl],      fmaf(a0, sw[128 + gl],      acc)));
        acc = fmaf(xi1, sw[16 + gl], fmaf(t1.y, sw[64 + 16 + gl], fmaf(a1, sw[128 + 16 + gl], acc)));
        acc = fmaf(xi2, sw[32 + gl], fmaf(t1.z, sw[64 + 32 + gl], fmaf(a2, sw[128 + 32 + gl], acc)));
        acc = fmaf(xi3, sw[48 + gl], fmaf(t1.w, sw[64 + 48 + gl], fmaf(a3, sw[128 + 48 + gl], acc)));
        v = fmaxf(acc, 0.f);
        x2[(size_t)node * 16 + gl] = v;
    }
    float vq = v * v;
    v  += __shfl_xor_sync(0xffffffffu, v, 16);
    vq += __shfl_xor_sync(0xffffffffu, vq, 16);
    if (lane < 16) {
        atomicAdd(&ssum[gl], v);
        atomicAdd(&ssq[gl], vq);
    }
    __syncthreads();
    if (tid < 16) {
        atomicAdd(&su3[tid], ssum[tid]);
        atomicAdd(&su3[16 + tid], ssq[tid]);
    }
}

// ---- prenormalize x2 -> half (F=16), stats from su3 ------------------------
__global__ void k_prenorm16(const float* __restrict__ x2, const float* __restrict__ su3,
                            __half* __restrict__ xn, int Ntot8, int N) {
    __shared__ float sm[16], srv[16];
    int tid = threadIdx.x;
    if (tid < 16) {
        float invn = 1.f / (float)N;
        float mm = su3[tid] * invn;
        float var = su3[16 + tid] * invn - mm * mm;
        if (var < 0.f) var = 0.f;
        sm[tid] = mm;
        srv[tid] = rsqrtf(var + 1e-5f);
    }
    __syncthreads();
    int i = blockIdx.x * blockDim.x + tid;
    if (i >= Ntot8) return;
    int f0 = (i & 7) * 2;
    float2 v = reinterpret_cast<const float2*>(x2)[i];
    float a = (v.x - sm[f0]) * srv[f0];
    float b = (v.y - sm[f0 + 1]) * srv[f0 + 1];
    reinterpret_cast<__half2*>(xn)[i] = __floats2half2_rn(a, b);
}

// ---- layer-3 SPMM: fp16 gather, one warp per node, 2-way pipelined ---------
// WRITE_H: write fp16 output; else fp32 output.
template<bool WRITE_H>
__global__ void k_spmm16h(const __half* __restrict__ z, __half* __restrict__ outh,
                          float* __restrict__ outf, int N) {
    int lane = threadIdx.x & 31;
    int node = (blockIdx.x * blockDim.x + threadIdx.x) >> 5;
    int eg = lane >> 1;
    int fl = lane & 1;

    int e0 = 0, e1 = 0;
    if (node < N) { e0 = g_off[node]; e1 = g_off[node + 1]; }

    float acc[8];
#pragma unroll
    for (int i = 0; i < 8; i++) acc[i] = 0.f;

    int e = e0 + eg;
    for (; e + 16 < e1; e += 32) {
        int2 eda = g_edge[e];
        int2 edb = g_edge[e + 16];
        float wa = __int_as_float(eda.y);
        float wb = __int_as_float(edb.y);
        int4 ta = *reinterpret_cast<const int4*>(z + (size_t)eda.x * 16 + fl * 8);
        int4 tb = *reinterpret_cast<const int4*>(z + (size_t)edb.x * 16 + fl * 8);
        float2 a0 = __half22float2(*reinterpret_cast<__half2*>(&ta.x));
        float2 a1 = __half22float2(*reinterpret_cast<__half2*>(&ta.y));
        float2 a2 = __half22float2(*reinterpret_cast<__half2*>(&ta.z));
        float2 a3 = __half22float2(*reinterpret_cast<__half2*>(&ta.w));
        float2 b0 = __half22float2(*reinterpret_cast<__half2*>(&tb.x));
        float2 b1 = __half22float2(*reinterpret_cast<__half2*>(&tb.y));
        float2 b2 = __half22float2(*reinterpret_cast<__half2*>(&tb.z));
        float2 b3 = __half22float2(*reinterpret_cast<__half2*>(&tb.w));
        acc[0] = fmaf(wa, a0.x, acc[0]); acc[0] = fmaf(wb, b0.x, acc[0]);
        acc[1] = fmaf(wa, a0.y, acc[1]); acc[1] = fmaf(wb, b0.y, acc[1]);
        acc[2] = fmaf(wa, a1.x, acc[2]); acc[2] = fmaf(wb, b1.x, acc[2]);
        acc[3] = fmaf(wa, a1.y, acc[3]); acc[3] = fmaf(wb, b1.y, acc[3]);
        acc[4] = fmaf(wa, a2.x, acc[4]); acc[4] = fmaf(wb, b2.x, acc[4]);
        acc[5] = fmaf(wa, a2.y, acc[5]); acc[5] = fmaf(wb, b2.y, acc[5]);
        acc[6] = fmaf(wa, a3.x, acc[6]); acc[6] = fmaf(wb, b3.x, acc[6]);
        acc[7] = fmaf(wa, a3.y, acc[7]); acc[7] = fmaf(wb, b3.y, acc[7]);
    }
    if (e < e1) {
        int2 eda = g_edge[e];
        float wa = __int_as_float(eda.y);
        int4 ta = *reinterpret_cast<const int4*>(z + (size_t)eda.x * 16 + fl * 8);
        float2 a0 = __half22float2(*reinterpret_cast<__half2*>(&ta.x));
        float2 a1 = __half22float2(*reinterpret_cast<__half2*>(&ta.y));
        float2 a2 = __half22float2(*reinterpret_cast<__half2*>(&ta.z));
        float2 a3 = __half22float2(*reinterpret_cast<__half2*>(&ta.w));
        acc[0] = fmaf(wa, a0.x, acc[0]);
        acc[1] = fmaf(wa, a0.y, acc[1]);
        acc[2] = fmaf(wa, a1.x, acc[2]);
        acc[3] = fmaf(wa, a1.y, acc[3]);
        acc[4] = fmaf(wa, a2.x, acc[4]);
        acc[5] = fmaf(wa, a2.y, acc[5]);
        acc[6] = fmaf(wa, a3.x, acc[6]);
        acc[7] = fmaf(wa, a3.y, acc[7]);
    }

#pragma unroll
    for (int s = 2; s < 32; s <<= 1) {
#pragma unroll
        for (int i = 0; i < 8; i++)
            acc[i] += __shfl_xor_sync(0xffffffffu, acc[i], s);
    }

    if (node < N && lane < 2) {
        if (WRITE_H) {
            __align__(16) __half2 h[4];
#pragma unroll
            for (int j = 0; j < 4; j++) h[j] = __floats2half2_rn(acc[2 * j], acc[2 * j + 1]);
            *reinterpret_cast<int4*>(outh + (size_t)node * 16 + fl * 8) =
                *reinterpret_cast<const int4*>(h);
        } else {
            float4* fp = reinterpret_cast<float4*>(outf + (size_t)node * 16 + fl * 8);
            fp[0] = make_float4(acc[0], acc[1], acc[2], acc[3]);
            fp[1] = make_float4(acc[4], acc[5], acc[6], acc[7]);
        }
    }
}

// ---- layer-3 combine: x2 fp32 + th3 fp16 + s2f fp32, 256 nodes/block -------
__global__ void __launch_bounds__(256) k_combine3(
    const float* __restrict__ x2, const float* __restrict__ su3,
    const __half* __restrict__ t1h, const float* __restrict__ s2,
    const float* __restrict__ W, const float* __restrict__ b,
    float* __restrict__ out, int N) {
    constexpr int FI = 16, FO = 64;
    __shared__ float sW[3 * FI * FO];
    __shared__ float sb[FO], sm[FI], srv[FI];
    for (int i = threadIdx.x; i < FI * FO; i += blockDim.x) {
        float w0 = W[i], w1 = W[FI * FO + i], w2 = W[2 * FI * FO + i];
        sW[i] = w0 - w2;
        sW[FI * FO + i] = w1;
        sW[2 * FI * FO + i] = 2.f * w2;
    }
    if ((int)threadIdx.x < FO) sb[threadIdx.x] = b[threadIdx.x];
    if ((int)threadIdx.x < FI) {
        float invn = 1.f / (float)N;
        float mm = su3[threadIdx.x] * invn;
        float var = su3[FI + threadIdx.x] * invn - mm * mm;
        if (var < 0.f) var = 0.f;
        sm[threadIdx.x] = mm;
        srv[threadIdx.x] = rsqrtf(var + 1e-5f);
    }
    __syncthreads();
    int node = blockIdx.x * blockDim.x + threadIdx.x;
    if (node >= N) return;

    float acc[FO];
#pragma unroll
    for (int j = 0; j < FO; j++) acc[j] = sb[j];

    const float4* xp = reinterpret_cast<const float4*>(x2 + (size_t)node * FI);
    const __half2* tp = reinterpret_cast<const __half2*>(t1h + (size_t)node * FI);
    const float4* sp = reinterpret_cast<const float4*>(s2 + (size_t)node * FI);

#pragma unroll 1
    for (int q = 0; q < 4; q++) {
        float4 xf = xp[q];
        float2 tf0 = __half22float2(tp[q * 2]);
        float2 tf1 = __half22float2(tp[q * 2 + 1]);
        float4 sf = sp[q];
        float xv[4] = {xf.x, xf.y, xf.z, xf.w};
        float tv[4] = {tf0.x, tf0.y, tf1.x, tf1.y};
        float sv[4] = {sf.x, sf.y, sf.z, sf.w};
#pragma unroll
        for (int h = 0; h < 4; h++) {
            int k = q * 4 + h;
            float xn = (xv[h] - sm[k]) * srv[k];
#pragma unroll
            for (int j = 0; j < FO; j++) {
                float w0 = sW[k * FO + j];
                float w1 = sW[FI * FO + k * FO + j];
                float w2 = sW[2 * FI * FO + k * FO + j];
                acc[j] = fmaf(xn, w0, fmaf(tv[h], w1, fmaf(sv[h], w2, acc[j])));
            }
        }
    }
    float4* op = reinterpret_cast<float4*>(out + (size_t)node * FO);
#pragma unroll
    for (int j = 0; j < FO / 4; j++)
        op[j] = make_float4(fmaxf(acc[4 * j], 0.f), fmaxf(acc[4 * j + 1], 0.f),
                            fmaxf(acc[4 * j + 2], 0.f), fmaxf(acc[4 * j + 3], 0.f));
}

// ---- layer4 projections; stats from su4 ------------------------------------
__global__ void k_uqr(const float* __restrict__ x3, const float* __restrict__ su4,
                      const float* __restrict__ W, int N) {
    __shared__ float wu[64], wq[64], wr[64], sm[64], srv[64];
    int t = threadIdx.x;
    if (t < 64) {
        float w0 = W[t], w1 = W[64 + t], w2 = W[128 + t];
        wu[t] = w0 - w2; wq[t] = w1; wr[t] = w2;
        float invn = 1.f / (float)N;
        float mm = su4[t] * invn;
        float var = su4[64 + t] * invn - mm * mm;
        if (var < 0.f) var = 0.f;
        sm[t] = mm;
        srv[t] = rsqrtf(var + 1e-5f);
    }
    __syncthreads();
    int n = blockIdx.x * blockDim.x + t;
    if (n >= N) return;
    float u = 0.f, q = 0.f, r = 0.f;
#pragma unroll
    for (int k = 0; k < 64; k++) {
        float xin = (x3[(size_t)n * 64 + k] - sm[k]) * srv[k];
        u = fmaf(xin, wu[k], u);
        q = fmaf(xin, wq[k], q);
        r = fmaf(xin, wr[k], r);
    }
    g_u[n] = u;
    *reinterpret_cast<float2*>(&g_qr[n * 2]) = make_float2(q, r);
}

// ---- node MLP: xs(85) -> 40 -> 16 -> 1; x4 + t=spmm(s) computed inline -----
__global__ void __launch_bounds__(128) k_nodemlp(
    const float* __restrict__ l1W, const float* __restrict__ l1b,
    const float* __restrict__ l2W, const float* __restrict__ l2b,
    const float* __restrict__ l3W, const float* __restrict__ l3b,
    const float* __restrict__ c4b, const float* __restrict__ tqs,
    float* __restrict__ xo, int N) {
    __shared__ float sW1[85 * 40], sb1[40], sW2[40 * 16], sb2[16], sW3[16], sb3[1], sb4[1];
    for (int i = threadIdx.x; i < 85 * 40; i += blockDim.x) sW1[i] = l1W[i];
    for (int i = threadIdx.x; i < 40 * 16; i += blockDim.x) sW2[i] = l2W[i];
    if (threadIdx.x < 40) sb1[threadIdx.x] = l1b[threadIdx.x];
    if (threadIdx.x < 16) { sb2[threadIdx.x] = l2b[threadIdx.x]; sW3[threadIdx.x] = l3W[threadIdx.x]; }
    if (threadIdx.x == 0) { sb3[0] = l3b[0]; sb4[0] = c4b[0]; }
    __syncthreads();

    int base = blockIdx.x * blockDim.x * 2 + threadIdx.x;
    int n0 = base, n1 = base + blockDim.x;
    bool v0ok = n0 < N, v1ok = n1 < N;

    // inline t = spmm(s), s = tqs[2r+1]
    float t0 = 0.f, t1v = 0.f;
    if (v0ok) {
        int e1 = g_off[n0 + 1];
        for (int e = g_off[n0]; e < e1; e++) {
            int2 ed = g_edge[e];
            t0 = fmaf(__int_as_float(ed.y), __ldg(&tqs[ed.x * 2 + 1]), t0);
        }
    }
    if (v1ok) {
        int e1 = g_off[n1 + 1];
        for (int e = g_off[n1]; e < e1; e++) {
            int2 ed = g_edge[e];
            t1v = fmaf(__int_as_float(ed.y), __ldg(&tqs[ed.x * 2 + 1]), t1v);
        }
    }

    float h1[2][40];
#pragma unroll
    for (int j = 0; j < 40; j++) { h1[0][j] = sb1[j]; h1[1][j] = sb1[j]; }

#pragma unroll 1
    for (int k = 0; k < 4; k++) {
        float a = v0ok ? g_x1[n0 * 4 + k] : 0.f;
        float bb = v1ok ? g_x1[n1 * 4 + k] : 0.f;
#pragma unroll
        for (int j = 0; j < 40; j++) {
            float w = sW1[k * 40 + j];
            h1[0][j] = fmaf(a, w, h1[0][j]);
            h1[1][j] = fmaf(bb, w, h1[1][j]);
        }
    }
#pragma unroll 1
    for (int k = 0; k < 16; k++) {
        float a = v0ok ? g_x2[n0 * 16 + k] : 0.f;
        float bb = v1ok ? g_x2[n1 * 16 + k] : 0.f;
#pragma unroll
        for (int j = 0; j < 40; j++) {
            float w = sW1[(4 + k) * 40 + j];
            h1[0][j] = fmaf(a, w, h1[0][j]);
            h1[1][j] = fmaf(bb, w, h1[1][j]);
        }
    }
#pragma unroll 1
    for (int k = 0; k < 64; k++) {
        float a = v0ok ? g_x3[n0 * 64 + k] : 0.f;
        float bb = v1ok ? g_x3[n1 * 64 + k] : 0.f;
#pragma unroll
        for (int j = 0; j < 40; j++) {
            float w = sW1[(20 + k) * 40 + j];
            h1[0][j] = fmaf(a, w, h1[0][j]);
            h1[1][j] = fmaf(bb, w, h1[1][j]);
        }
    }
    {   // x4 = relu(u + Tq + 2*t + cheb4_b)
        float a = v0ok ? fmaxf(g_u[n0] + tqs[n0 * 2] + 2.f * t0 + sb4[0], 0.f) : 0.f;
        float bb = v1ok ? fmaxf(g_u[n1] + tqs[n1 * 2] + 2.f * t1v + sb4[0], 0.f) : 0.f;
#pragma unroll
        for (int j = 0; j < 40; j++) {
            float w = sW1[84 * 40 + j];
            h1[0][j] = fmaf(a, w, h1[0][j]);
            h1[1][j] = fmaf(bb, w, h1[1][j]);
        }
    }
#pragma unroll
    for (int j = 0; j < 40; j++) { h1[0][j] = fmaxf(h1[0][j], 0.f); h1[1][j] = fmaxf(h1[1][j], 0.f); }

    float h2[2][16];
#pragma unroll
    for (int j = 0; j < 16; j++) { h2[0][j] = sb2[j]; h2[1][j] = sb2[j]; }
#pragma unroll
    for (int k = 0; k < 40; k++) {
        float a = h1[0][k], bb = h1[1][k];
#pragma unroll
        for (int j = 0; j < 16; j++) {
            float w = sW2[k * 16 + j];
            h2[0][j] = fmaf(a, w, h2[0][j]);
            h2[1][j] = fmaf(bb, w, h2[1][j]);
        }
    }
    float o0 = sb3[0], o1 = sb3[0];
#pragma unroll
    for (int k = 0; k < 16; k++) {
        float w = sW3[k];
        o0 = fmaf(fmaxf(h2[0][k], 0.f), w, o0);
        o1 = fmaf(fmaxf(h2[1][k], 0.f), w, o1);
    }
    if (v0ok) xo[n0] = fmaxf(o0, 0.f);
    if (v1ok) xo[n1] = fmaxf(o1, 0.f);
}

// ---- edge MLPs (4 edges per thread) ----------------------------------------
__device__ __forceinline__ float edge_mlp(float s, float d, float a,
                                          const float* __restrict__ w1,
                                          const float* __restrict__ b1,
                                          const float* __restrict__ g,
                                          const float* __restrict__ be,
                                          const float* __restrict__ w2,
                                          const float* __restrict__ b2) {
    float h0 = fmaf(s, __ldg(&w1[0]), fmaf(d, __ldg(&w1[2]), fmaf(a, __ldg(&w1[4]), __ldg(&b1[0]))));
    float h1 = fmaf(s, __ldg(&w1[1]), fmaf(d, __ldg(&w1[3]), fmaf(a, __ldg(&w1[5]), __ldg(&b1[1]))));
    h0 = fmaxf(h0, 0.f);
    h1 = fmaxf(h1, 0.f);
    float m = 0.5f * (h0 + h1);
    float d0 = h0 - m, d1 = h1 - m;
    float var = 0.5f * (d0 * d0 + d1 * d1);
    float rs = rsqrtf(var + 1e-5f);
    h0 = fmaf(d0 * rs, __ldg(&g[0]), 0.f) + __ldg(&be[0]);
    h1 = fmaf(d1 * rs, __ldg(&g[1]), 0.f) + __ldg(&be[1]);
    return fmaf(h0, __ldg(&w2[0]), fmaf(h1, __ldg(&w2[1]), __ldg(&b2[0])));
}

__global__ void k_edge(const int* __restrict__ ei, const float* __restrict__ ea,
                       const float* __restrict__ xo,
                       const float* __restrict__ w11, const float* __restrict__ b11,
                       const float* __restrict__ g1, const float* __restrict__ be1,
                       const float* __restrict__ w12, const float* __restrict__ b12,
                       const float* __restrict__ w21, const float* __restrict__ b21,
                       const float* __restrict__ g2, const float* __restrict__ be2,
                       const float* __restrict__ w22, const float* __restrict__ b22,
                       float* __restrict__ out, int E) {
    int e0 = (blockIdx.x * blockDim.x + threadIdx.x) * 4;
    if (e0 >= E) return;
    if (e0 + 3 < E) {
        int4 rr = *reinterpret_cast<const int4*>(ei + e0);
        int4 cc = *reinterpret_cast<const int4*>(ei + E + e0);
        float4 aa = *reinterpret_cast<const float4*>(ea + e0);
        int rA[4] = {rr.x, rr.y, rr.z, rr.w};
        int cA[4] = {cc.x, cc.y, cc.z, cc.w};
        float aA[4] = {aa.x, aa.y, aa.z, aa.w};
        float oA[4];
#pragma unroll
        for (int i = 0; i < 4; i++) {
            float s = __ldg(&xo[rA[i]]);
            float d = __ldg(&xo[cA[i]]);
            float o1 = fmaxf(edge_mlp(s, d, aA[i], w11, b11, g1, be1, w12, b12), 0.f);
            oA[i] = fmaxf(edge_mlp(s, d, o1, w21, b21, g2, be2, w22, b22), 0.f);
        }
        *reinterpret_cast<float4*>(out + e0) = make_float4(oA[0], oA[1], oA[2], oA[3]);
    } else {
        for (int e = e0; e < E; e++) {
            int r = ei[e];
            int c = ei[E + e];
            float s = __ldg(&xo[r]);
            float d = __ldg(&xo[c]);
            float a = ea[e];
            float o1 = fmaxf(edge_mlp(s, d, a, w11, b11, g1, be1, w12, b12), 0.f);
            out[e] = fmaxf(edge_mlp(s, d, o1, w21, b21, g2, be2, w22, b22), 0.f);
        }
    }
}

// ---------------------------------------------------------------------------
extern "C" void kernel_launch(void* const* d_in, const int* in_sizes, int n_in,
                              void* d_out, int out_size) {
    (void)n_in; (void)out_size;
    const float* x   = (const float*)d_in[0];
    const int*   ei  = (const int*)d_in[1];
    const float* ea  = (const float*)d_in[2];
    const float* c1W = (const float*)d_in[3];  const float* c1b = (const float*)d_in[4];
    const float* c2W = (const float*)d_in[5];  const float* c2b = (const float*)d_in[6];
    const float* c3W = (const float*)d_in[7];  const float* c3b = (const float*)d_in[8];
    const float* c4W = (const float*)d_in[9];  const float* c4b = (const float*)d_in[10];
    const float* l1W = (const float*)d_in[11]; const float* l1b = (const float*)d_in[12];
    const float* l2W = (const float*)d_in[13]; const float* l2b = (const float*)d_in[14];
    const float* l3W = (const float*)d_in[15]; const float* l3b = (const float*)d_in[16];
    const float* e1w1 = (const float*)d_in[17]; const float* e1b1 = (const float*)d_in[18];
    const float* e1g  = (const float*)d_in[19]; const float* e1be = (const float*)d_in[20];
    const float* e1w2 = (const float*)d_in[21]; const float* e1b2 = (const float*)d_in[22];
    const float* e2w1 = (const float*)d_in[23]; const float* e2b1 = (const float*)d_in[24];
    const float* e2g  = (const float*)d_in[25]; const float* e2be = (const float*)d_in[26];
    const float* e2w2 = (const float*)d_in[27]; const float* e2b2 = (const float*)d_in[28];

    int N = in_sizes[0];
    int E = in_sizes[1] / 2;
    float* out = (float*)d_out;
    float* xo = out;
    float* eaout = out + N;

    void* p;
    float *sums, *x1, *x2, *x3, *tx1, *s2f, *qr, *tqs;
    __half *xn3, *th3;
    cudaGetSymbolAddress(&p, g_sums); sums = (float*)p;
    cudaGetSymbolAddress(&p, g_x1);   x1   = (float*)p;
    cudaGetSymbolAddress(&p, g_x2);   x2   = (float*)p;
    cudaGetSymbolAddress(&p, g_x3);   x3   = (float*)p;
    cudaGetSymbolAddress(&p, g_tx1);  tx1  = (float*)p;
    cudaGetSymbolAddress(&p, g_s2f);  s2f  = (float*)p;
    cudaGetSymbolAddress(&p, g_qr);   qr   = (float*)p;
    cudaGetSymbolAddress(&p, g_tqs);  tqs  = (float*)p;
    cudaGetSymbolAddress(&p, g_xn3);  xn3  = (__half*)p;
    cudaGetSymbolAddress(&p, g_th3);  th3  = (__half*)p;

    int gN = (N + 255) / 256;
    int NB = (N + 511) / 512;
    int gE2 = (E / 2 + 255) / 256 + 1;
    int gE4 = (E / 4 + 255) / 256 + 1;

    auto spmm_grid = [](int n, int group) {
        int npw = 32 / group;
        long long warps = (n + npw - 1) / npw;
        return (int)((warps * 32 + 255) / 256);
    };
    int gWarp = (int)(((long long)N * 32 + 255) / 256);   // 1 warp per node

    float* su1 = sums + 0;
    float* su2 = sums + 2;
    float* su3 = sums + 10;
    float* su4 = sums + 42;

    // ---- preprocessing ----
    k_zero<<<gN, 256>>>(N);
    k_count<<<gE2, 256>>>(ei, ea, E);
    k_scanA<<<NB, 512>>>(N);
    k_scanC<<<gN, 256>>>(x, N, E, su1);
    k_scatter<<<gE2, 256>>>(ei, ea, E);

    // ---- layer 1: 1 -> 4 ----
    k_spmm<1, 1, 4, true><<<spmm_grid(N, 4), 256>>>(x, su1, tx1, N, 1, 1);
    k_fuse1<<<(N * 4 + 255) / 256, 256>>>(x, su1, tx1, c1W, c1b, x1, su2, N);

    // ---- layer 2: 4 -> 16 ----
    k_spmm<4, 4, 16, true><<<spmm_grid(N, 16), 256>>>(x1, su2, tx1, N, 4, 4);
    k_fuse2<<<(N + 15) / 16, 256>>>(x1, su2, tx1, c2W, c2b, x2, su3, N);

    // ---- layer 3: 16 -> 64 (fp16 gathers; combine reads x2 f32 / th3 h / s2f f32) ----
    k_prenorm16<<<(N * 8 + 255) / 256, 256>>>(x2, su3, xn3, N * 8, N);
    k_spmm16h<true ><<<gWarp, 256>>>(xn3, th3, nullptr, N);  // th3 (fp16 only)
    k_spmm16h<false><<<gWarp, 256>>>(th3, nullptr, s2f, N);  // s2f (fp32 only)
    k_combine3<<<gN, 256>>>(x2, su3, th3, s2f, c3W, c3b, x3, N);

    // ---- layer 4: 64 -> 1 via spmm/matmul commute ----
    k_reduce<64><<<512, 256>>>(x3, su4, N);
    k_uqr<<<gN, 256>>>(x3, su4, c4W, N);
    k_spmm<2, 2, 8, false><<<spmm_grid(N, 8), 256>>>(qr, nullptr, tqs, N, 2, 2);  // (Tq, s)
    // t = spmm(s) is computed inline inside k_nodemlp.

    // ---- node MLP (with inline t) and edge MLPs ----
    k_nodemlp<<<gN, 128>>>(l1W, l1b, l2W, l2b, l3W, l3b, c4b, tqs, xo, N);
    k_edge<<<gE4, 256>>>(ei, ea, xo,
                        e1w1, e1b1, e1g, e1be, e1w2, e1b2,
                        e2w1, e2b1, e2g, e2be, e2w2, e2b2,
                        eaout, E);
}

// round 16
// speedup vs baseline: 1.0235x; 1.0235x over previous
#include <cuda_runtime.h>
#include <cuda_fp16.h>

// ---------------------------------------------------------------------------
// AggNet: 4x ChebConv(K=3) + node MLP + 2x edge MLP, N=200K, E=3.2M.
// R15 (resubmit after infra failure): R13 baseline (best safe: 671.8us @
// 1.89e-4) + 4-edges-per-thread k_edge only. R14's inline-t-in-nodemlp
// reverted (serial dependent gather preamble at 128 threads/block lost).
// ---------------------------------------------------------------------------

static constexpr int NMAX = 200000;
static constexpr int EMAX = 3200000;

// -------- static device scratch ---------------------------------------------
__device__ int2  g_edge[EMAX];      // (row, wn-bits) sorted by col
__device__ int   g_off[NMAX + 1];
__device__ int   g_cursor[NMAX];
__device__ int   g_cnt[NMAX];
__device__ float g_deg[NMAX];
__device__ float g_rdis[NMAX];
__device__ int   g_part[1024];

__device__ float g_x1[NMAX * 4];
__device__ float g_x2[NMAX * 16];
__device__ float g_x3[NMAX * 64];
__device__ float g_tx1[NMAX * 16];  // fp32 Tx1 scratch (layers 1,2)
__device__ float g_s2f[NMAX * 16];  // fp32 spmm(Tx1) for layer 3 combine
__device__ __align__(16) __half g_xn3[NMAX * 16];  // normalized x2, fp16
__device__ __align__(16) __half g_th3[NMAX * 16];  // Tx1 (layer3), fp16
__device__ float g_u[NMAX];
__device__ float g_qr[NMAX * 2];    // (q, r) interleaved
__device__ float g_tqs[NMAX * 2];   // (Tq, s) interleaved
__device__ float g_t[NMAX];
__device__ float g_sums[192];       // su1@0(2) su2@2(8) su3@10(32) su4@42(128)

// ---------------------------------------------------------------------------
__global__ void k_zero(int N) {
    int i = blockIdx.x * blockDim.x + threadIdx.x;
    if (i < N) { g_cnt[i] = 0; g_deg[i] = 0.f; }
    if (i < 192) g_sums[i] = 0.f;
}

__global__ void k_count(const int* __restrict__ ei, const float* __restrict__ ea, int E) {
    int e0 = (blockIdx.x * blockDim.x + threadIdx.x) * 2;
    if (e0 >= E) return;
    if (e0 + 1 < E) {
        int2 rr = *reinterpret_cast<const int2*>(ei + e0);
        int2 cc = *reinterpret_cast<const int2*>(ei + E + e0);
        float2 aa = *reinterpret_cast<const float2*>(ea + e0);
        atomicAdd(&g_cnt[cc.x], 1);
        atomicAdd(&g_cnt[cc.y], 1);
        atomicAdd(&g_deg[rr.x], aa.x);
        atomicAdd(&g_deg[rr.y], aa.y);
    } else {
        atomicAdd(&g_cnt[ei[E + e0]], 1);
        atomicAdd(&g_deg[ei[e0]], ea[e0]);
    }
}

// ---- scanA: per-512-tile local exclusive + tile aggregates ------------------
__global__ void k_scanA(int n) {
    __shared__ int sd[512];
    int i = blockIdx.x * 512 + threadIdx.x;
    int v = (i < n) ? g_cnt[i] : 0;
    sd[threadIdx.x] = v;
    __syncthreads();
    for (int s = 1; s < 512; s <<= 1) {
        int t = (threadIdx.x >= s) ? sd[threadIdx.x - s] : 0;
        __syncthreads();
        sd[threadIdx.x] += t;
        __syncthreads();
    }
    if (i < n) g_off[i] = sd[threadIdx.x] - v;
    if (threadIdx.x == 511) g_part[blockIdx.x] = sd[511];
}

// ---- scanC: tile prefix (per-block sum of g_part), offsets, rdis, su1 ------
__global__ void k_scanC(const float* __restrict__ x, int n, int e, float* __restrict__ su1) {
    __shared__ int pr[256];
    __shared__ float ss[2];
    int tid = threadIdx.x;
    if (tid < 2) ss[tid] = 0.f;

    int t0 = blockIdx.x >> 1;       // 512-wide scanA tile containing this block
    int part = 0;
    for (int j = tid; j < t0; j += 256) part += g_part[j];
    pr[tid] = part;
    __syncthreads();
    for (int s = 128; s; s >>= 1) {
        if (tid < s) pr[tid] += pr[tid + s];
        __syncthreads();
    }
    int pre = pr[0];

    int i = blockIdx.x * 256 + tid;
    float v = 0.f;
    if (i < n) {
        int o = g_off[i] + pre;
        g_off[i] = o;
        g_cursor[i] = o;
        float d = g_deg[i];
        g_rdis[i] = (d > 0.f) ? rsqrtf(d) : 0.f;
        v = x[i];
    }
    if (i == 0) g_off[n] = e;
    float s = v, s2 = v * v;
#pragma unroll
    for (int m = 16; m; m >>= 1) {
        s  += __shfl_xor_sync(0xffffffffu, s, m);
        s2 += __shfl_xor_sync(0xffffffffu, s2, m);
    }
    if ((tid & 31) == 0) { atomicAdd(&ss[0], s); atomicAdd(&ss[1], s2); }
    __syncthreads();
    if (tid == 0) { atomicAdd(&su1[0], ss[0]); atomicAdd(&su1[1], ss[1]); }
}

__global__ void k_scatter(const int* __restrict__ ei, const float* __restrict__ ea, int E) {
    int e0 = (blockIdx.x * blockDim.x + threadIdx.x) * 2;
    if (e0 >= E) return;
    if (e0 + 1 < E) {
        int2 rr = *reinterpret_cast<const int2*>(ei + e0);
        int2 cc = *reinterpret_cast<const int2*>(ei + E + e0);
        float2 aa = *reinterpret_cast<const float2*>(ea + e0);
        int p0 = atomicAdd(&g_cursor[cc.x], 1);
        g_edge[p0] = make_int2(rr.x, __float_as_int(-g_rdis[rr.x] * aa.x * g_rdis[cc.x]));
        int p1 = atomicAdd(&g_cursor[cc.y], 1);
        g_edge[p1] = make_int2(rr.y, __float_as_int(-g_rdis[rr.y] * aa.y * g_rdis[cc.y]));
    } else {
        int r = ei[e0];
        int c = ei[E + e0];
        int p = atomicAdd(&g_cursor[c], 1);
        g_edge[p] = make_int2(r, __float_as_int(-g_rdis[r] * ea[e0] * g_rdis[c]));
    }
}

// ---- raw-sum reduction for layer-4 stats (x3, F=64) ------------------------
template<int F>
__global__ void k_reduce(const float* __restrict__ x, float* __restrict__ sums, int N) {
    constexpr int G = 256 / F;
    int f = threadIdx.x & (F - 1);
    int g = threadIdx.x / F;
    float s = 0.f, s2 = 0.f;
    for (int n = blockIdx.x * G + g; n < N; n += gridDim.x * G) {
        float v = x[n * F + f];
        s += v;
        s2 += v * v;
    }
    __shared__ float rs[256], rq[256];
    rs[threadIdx.x] = s;
    rq[threadIdx.x] = s2;
    __syncthreads();
    for (int step = 128; step >= F; step >>= 1) {
        if ((int)threadIdx.x < step) {
            rs[threadIdx.x] += rs[threadIdx.x + step];
            rq[threadIdx.x] += rq[threadIdx.x + step];
        }
        __syncthreads();
    }
    if ((int)threadIdx.x < F) {
        atomicAdd(&sums[f], rs[f]);
        atomicAdd(&sums[F + f], rq[f]);
    }
}

// ---- vector load helper ----------------------------------------------------
template<int VEC>
__device__ __forceinline__ void loadvec(float* v, const float* p) {
    if (VEC == 4) {
        float4 t = *reinterpret_cast<const float4*>(p);
        v[0] = t.x; v[1] = t.y; v[2] = t.z; v[3] = t.w;
    } else if (VEC == 2) {
        float2 t = *reinterpret_cast<const float2*>(p);
        v[0] = t.x; v[1] = t.y;
    } else {
        v[0] = *p;
    }
}

// ---- generic vectorized SPMM; NORM computes stats from raw sums ------------
template<int F, int VEC, int GROUP, bool NORM>
__global__ void k_spmm(const float* __restrict__ z, const float* __restrict__ sums,
                       float* __restrict__ out, int N, int zs, int os) {
    constexpr int LPE = F / VEC;
    constexpr int EPI = GROUP / LPE;
    constexpr int NPW = 32 / GROUP;

    int lane = threadIdx.x & 31;
    int wid  = (blockIdx.x * blockDim.x + threadIdx.x) >> 5;
    int sub  = lane / GROUP;
    int gl   = lane % GROUP;
    int eg   = gl / LPE;
    int fl   = gl % LPE;

    int node = wid * NPW + sub;

    float m[VEC], rv[VEC];
#pragma unroll
    for (int i = 0; i < VEC; i++) { m[i] = 0.f; rv[i] = 1.f; }
    if (NORM) {
        float invn = 1.f / (float)N;
#pragma unroll
        for (int i = 0; i < VEC; i++) {
            int f = fl * VEC + i;
            float mm = sums[f] * invn;
            float var = sums[F + f] * invn - mm * mm;
            if (var < 0.f) var = 0.f;
            m[i] = mm;
            rv[i] = rsqrtf(var + 1e-5f);
        }
    }

    int e0 = 0, e1 = 0;
    if (node < N) { e0 = g_off[node]; e1 = g_off[node + 1]; }

    float acc[VEC];
#pragma unroll
    for (int i = 0; i < VEC; i++) acc[i] = 0.f;

    int e = e0 + eg;
    for (; e + EPI < e1; e += 2 * EPI) {
        int2 ed0 = g_edge[e];
        int2 ed1 = g_edge[e + EPI];
        float w0 = __int_as_float(ed0.y);
        float w1 = __int_as_float(ed1.y);
        float v0[VEC], v1[VEC];
        loadvec<VEC>(v0, z + (size_t)ed0.x * zs + fl * VEC);
        loadvec<VEC>(v1, z + (size_t)ed1.x * zs + fl * VEC);
#pragma unroll
        for (int i = 0; i < VEC; i++) {
            float a = NORM ? (v0[i] - m[i]) * rv[i] : v0[i];
            float b = NORM ? (v1[i] - m[i]) * rv[i] : v1[i];
            acc[i] = fmaf(w0, a, acc[i]);
            acc[i] = fmaf(w1, b, acc[i]);
        }
    }
    if (e < e1) {
        int2 ed = g_edge[e];
        float w = __int_as_float(ed.y);
        float v[VEC];
        loadvec<VEC>(v, z + (size_t)ed.x * zs + fl * VEC);
#pragma unroll
        for (int i = 0; i < VEC; i++) {
            float a = NORM ? (v[i] - m[i]) * rv[i] : v[i];
            acc[i] = fmaf(w, a, acc[i]);
        }
    }

#pragma unroll
    for (int s = LPE; s < GROUP; s <<= 1) {
#pragma unroll
        for (int i = 0; i < VEC; i++)
            acc[i] += __shfl_xor_sync(0xffffffffu, acc[i], s);
    }

    if (node < N && eg == 0) {
        float* op = out + (size_t)node * os + fl * VEC;
        if (VEC == 4) {
            *reinterpret_cast<float4*>(op) = make_float4(acc[0], acc[1], acc[2], acc[3]);
        } else if (VEC == 2) {
            *reinterpret_cast<float2*>(op) = make_float2(acc[0], acc[1]);
        } else {
            *op = acc[0];
        }
    }
}

// ---- fused layer-1 pass2 + combine + su2 stats (4 lanes/node, 2-way) -------
__global__ void k_fuse1(const float* __restrict__ x, const float* __restrict__ su1,
                        const float* __restrict__ tx1,
                        const float* __restrict__ W, const float* __restrict__ b,
                        float* __restrict__ x1, float* __restrict__ su2, int N) {
    __shared__ float sw[12], sb[4], ssum[4], ssq[4];
    int tid = threadIdx.x;
    if (tid < 4) {
        sw[tid] = W[tid] - W[8 + tid];
        sw[4 + tid] = W[4 + tid];
        sw[8 + tid] = 2.f * W[8 + tid];
        sb[tid] = b[tid];
        ssum[tid] = 0.f;
        ssq[tid] = 0.f;
    }
    __syncthreads();
    int lane = tid & 31;
    int wid = (blockIdx.x * blockDim.x + tid) >> 5;
    int sub = lane >> 2;        // 8 nodes per warp
    int gl = lane & 3;          // 4 edge slots -> later feature index
    int node = wid * 8 + sub;
    bool valid = node < N;
    int e0 = 0, e1 = 0;
    if (valid) { e0 = g_off[node]; e1 = g_off[node + 1]; }
    float acc = 0.f;
    int e = e0 + gl;
    for (; e + 4 < e1; e += 8) {
        int2 a = g_edge[e];
        int2 b2 = g_edge[e + 4];
        float za = __ldg(&tx1[a.x]);
        float zb = __ldg(&tx1[b2.x]);
        acc = fmaf(__int_as_float(a.y), za, acc);
        acc = fmaf(__int_as_float(b2.y), zb, acc);
    }
    if (e < e1) {
        int2 a = g_edge[e];
        acc = fmaf(__int_as_float(a.y), __ldg(&tx1[a.x]), acc);
    }
    acc += __shfl_xor_sync(0xffffffffu, acc, 1);
    acc += __shfl_xor_sync(0xffffffffu, acc, 2);

    float v = 0.f;
    if (valid) {
        float invn = 1.f / (float)N;
        float mm = su1[0] * invn;
        float var = su1[1] * invn - mm * mm;
        if (var < 0.f) var = 0.f;
        float rv = rsqrtf(var + 1e-5f);
        float xin = (x[node] - mm) * rv;
        float t1 = tx1[node];
        v = fmaxf(fmaf(xin, sw[gl], fmaf(t1, sw[4 + gl], fmaf(acc, sw[8 + gl], sb[gl]))), 0.f);
        x1[(size_t)node * 4 + gl] = v;
    }
    float vq = v * v;
#pragma unroll
    for (int s = 4; s < 32; s <<= 1) {
        v  += __shfl_xor_sync(0xffffffffu, v,  s);
        vq += __shfl_xor_sync(0xffffffffu, vq, s);
    }
    if (lane < 4) {
        atomicAdd(&ssum[gl], v);
        atomicAdd(&ssq[gl], vq);
    }
    __syncthreads();
    if (tid < 4) {
        atomicAdd(&su2[tid], ssum[tid]);
        atomicAdd(&su2[4 + tid], ssq[tid]);
    }
}

// ---- fused layer-2 pass2 + combine + su3 stats (16 lanes/node, 2-way) ------
__global__ void k_fuse2(const float* __restrict__ x1, const float* __restrict__ su2,
                        const float* __restrict__ tx1,
                        const float* __restrict__ W, const float* __restrict__ b,
                        float* __restrict__ x2, float* __restrict__ su3, int N) {
    __shared__ float sw[192], sb[16], sm[4], srv[4], ssum[16], ssq[16];
    int tid = threadIdx.x;
    for (int i = tid; i < 64; i += blockDim.x) {
        sw[i] = W[i] - W[128 + i];
        sw[64 + i] = W[64 + i];
        sw[128 + i] = 2.f * W[128 + i];
    }
    if (tid < 16) { sb[tid] = b[tid]; ssum[tid] = 0.f; ssq[tid] = 0.f; }
    if (tid < 4) {
        float invn = 1.f / (float)N;
        float mm = su2[tid] * invn;
        float var = su2[4 + tid] * invn - mm * mm;
        if (var < 0.f) var = 0.f;
        sm[tid] = mm;
        srv[tid] = rsqrtf(var + 1e-5f);
    }
    __syncthreads();
    int lane = tid & 31;
    int wid = (blockIdx.x * blockDim.x + tid) >> 5;
    int sub = lane >> 4;
    int gl = lane & 15;
    int node = wid * 2 + sub;
    bool valid = node < N;
    int e0 = 0, e1 = 0;
    if (valid) { e0 = g_off[node]; e1 = g_off[node + 1]; }
    float a0 = 0.f, a1 = 0.f, a2 = 0.f, a3 = 0.f;
    int e = e0 + gl;
    for (; e + 16 < e1; e += 32) {
        int2 eda = g_edge[e];
        int2 edb = g_edge[e + 16];
        float wa = __int_as_float(eda.y);
        float wb = __int_as_float(edb.y);
        float4 ta = *reinterpret_cast<const float4*>(tx1 + (size_t)eda.x * 4);
        float4 tb = *reinterpret_cast<const float4*>(tx1 + (size_t)edb.x * 4);
        a0 = fmaf(wa, ta.x, a0); a0 = fmaf(wb, tb.x, a0);
        a1 = fmaf(wa, ta.y, a1); a1 = fmaf(wb, tb.y, a1);
        a2 = fmaf(wa, ta.z, a2); a2 = fmaf(wb, tb.z, a2);
        a3 = fmaf(wa, ta.w, a3); a3 = fmaf(wb, tb.w, a3);
    }
    if (e < e1) {
        int2 eda = g_edge[e];
        float wa = __int_as_float(eda.y);
        float4 ta = *reinterpret_cast<const float4*>(tx1 + (size_t)eda.x * 4);
        a0 = fmaf(wa, ta.x, a0);
        a1 = fmaf(wa, ta.y, a1);
        a2 = fmaf(wa, ta.z, a2);
        a3 = fmaf(wa, ta.w, a3);
    }
#pragma unroll
    for (int s = 1; s < 16; s <<= 1) {
        a0 += __shfl_xor_sync(0xffffffffu, a0, s);
        a1 += __shfl_xor_sync(0xffffffffu, a1, s);
        a2 += __shfl_xor_sync(0xffffffffu, a2, s);
        a3 += __shfl_xor_sync(0xffffffffu, a3, s);
    }
    float v = 0.f;
    if (valid) {
        float4 t1 = *reinterpret_cast<const float4*>(tx1 + (size_t)node * 4);
        float xi0 = (x1[(size_t)node * 4 + 0] - sm[0]) * srv[0];
        float xi1 = (x1[(size_t)node * 4 + 1] - sm[1]) * srv[1];
        float xi2 = (x1[(size_t)node * 4 + 2] - sm[2]) * srv[2];
        float xi3 = (x1[(size_t)node * 4 + 3] - sm[3]) * srv[3];
        float acc = sb[gl];
        acc = fmaf(xi0, sw[gl],      fmaf(t1.x, sw[64 + gl],      fmaf(a0, sw[128 + gl],      acc)));
        acc = fmaf(xi1, sw[16 + gl], fmaf(t1.y, sw[64 + 16 + gl], fmaf(a1, sw[128 + 16 + gl], acc)));
        acc = fmaf(xi2, sw[32 + gl], fmaf(t1.z, sw[64 + 32 + gl], fmaf(a2, sw[128 + 32 + gl], acc)));
        acc = fmaf(xi3, sw[48 + gl], fmaf(t1.w, sw[64 + 48 + gl], fmaf(a3, sw[128 + 48 + gl], acc)));
        v = fmaxf(acc, 0.f);
        x2[(size_t)node * 16 + gl] = v;
    }
    float vq = v * v;
    v  += __shfl_xor_sync(0xffffffffu, v, 16);
    vq += __shfl_xor_sync(0xffffffffu, vq, 16);
    if (lane < 16) {
        atomicAdd(&ssum[gl], v);
        atomicAdd(&ssq[gl], vq);
    }
    __syncthreads();
    if (tid < 16) {
        atomicAdd(&su3[tid], ssum[tid]);
        atomicAdd(&su3[16 + tid], ssq[tid]);
    }
}

// ---- prenormalize x2 -> half (F=16), stats from su3 ------------------------
__global__ void k_prenorm16(const float* __restrict__ x2, const float* __restrict__ su3,
                            __half* __restrict__ xn, int Ntot8, int N) {
    __shared__ float sm[16], srv[16];
    int tid = threadIdx.x;
    if (tid < 16) {
        float invn = 1.f / (float)N;
        float mm = su3[tid] * invn;
        float var = su3[16 + tid] * invn - mm * mm;
        if (var < 0.f) var = 0.f;
        sm[tid] = mm;
        srv[tid] = rsqrtf(var + 1e-5f);
    }
    __syncthreads();
    int i = blockIdx.x * blockDim.x + tid;
    if (i >= Ntot8) return;
    int f0 = (i & 7) * 2;
    float2 v = reinterpret_cast<const float2*>(x2)[i];
    float a = (v.x - sm[f0]) * srv[f0];
    float b = (v.y - sm[f0 + 1]) * srv[f0 + 1];
    reinterpret_cast<__half2*>(xn)[i] = __floats2half2_rn(a, b);
}

// ---- layer-3 SPMM: fp16 gather, one warp per node, 2-way pipelined ---------
// WRITE_H: write fp16 output; else fp32 output.
template<bool WRITE_H>
__global__ void k_spmm16h(const __half* __restrict__ z, __half* __restrict__ outh,
                          float* __restrict__ outf, int N) {
    int lane = threadIdx.x & 31;
    int node = (blockIdx.x * blockDim.x + threadIdx.x) >> 5;
    int eg = lane >> 1;
    int fl = lane & 1;

    int e0 = 0, e1 = 0;
    if (node < N) { e0 = g_off[node]; e1 = g_off[node + 1]; }

    float acc[8];
#pragma unroll
    for (int i = 0; i < 8; i++) acc[i] = 0.f;

    int e = e0 + eg;
    for (; e + 16 < e1; e += 32) {
        int2 eda = g_edge[e];
        int2 edb = g_edge[e + 16];
        float wa = __int_as_float(eda.y);
        float wb = __int_as_float(edb.y);
        int4 ta = *reinterpret_cast<const int4*>(z + (size_t)eda.x * 16 + fl * 8);
        int4 tb = *reinterpret_cast<const int4*>(z + (size_t)edb.x * 16 + fl * 8);
        float2 a0 = __half22float2(*reinterpret_cast<__half2*>(&ta.x));
        float2 a1 = __half22float2(*reinterpret_cast<__half2*>(&ta.y));
        float2 a2 = __half22float2(*reinterpret_cast<__half2*>(&ta.z));
        float2 a3 = __half22float2(*reinterpret_cast<__half2*>(&ta.w));
        float2 b0 = __half22float2(*reinterpret_cast<__half2*>(&tb.x));
        float2 b1 = __half22float2(*reinterpret_cast<__half2*>(&tb.y));
        float2 b2 = __half22float2(*reinterpret_cast<__half2*>(&tb.z));
        float2 b3 = __half22float2(*reinterpret_cast<__half2*>(&tb.w));
        acc[0] = fmaf(wa, a0.x, acc[0]); acc[0] = fmaf(wb, b0.x, acc[0]);
        acc[1] = fmaf(wa, a0.y, acc[1]); acc[1] = fmaf(wb, b0.y, acc[1]);
        acc[2] = fmaf(wa, a1.x, acc[2]); acc[2] = fmaf(wb, b1.x, acc[2]);
        acc[3] = fmaf(wa, a1.y, acc[3]); acc[3] = fmaf(wb, b1.y, acc[3]);
        acc[4] = fmaf(wa, a2.x, acc[4]); acc[4] = fmaf(wb, b2.x, acc[4]);
        acc[5] = fmaf(wa, a2.y, acc[5]); acc[5] = fmaf(wb, b2.y, acc[5]);
        acc[6] = fmaf(wa, a3.x, acc[6]); acc[6] = fmaf(wb, b3.x, acc[6]);
        acc[7] = fmaf(wa, a3.y, acc[7]); acc[7] = fmaf(wb, b3.y, acc[7]);
    }
    if (e < e1) {
        int2 eda = g_edge[e];
        float wa = __int_as_float(eda.y);
        int4 ta = *reinterpret_cast<const int4*>(z + (size_t)eda.x * 16 + fl * 8);
        float2 a0 = __half22float2(*reinterpret_cast<__half2*>(&ta.x));
        float2 a1 = __half22float2(*reinterpret_cast<__half2*>(&ta.y));
        float2 a2 = __half22float2(*reinterpret_cast<__half2*>(&ta.z));
        float2 a3 = __half22float2(*reinterpret_cast<__half2*>(&ta.w));
        acc[0] = fmaf(wa, a0.x, acc[0]);
        acc[1] = fmaf(wa, a0.y, acc[1]);
        acc[2] = fmaf(wa, a1.x, acc[2]);
        acc[3] = fmaf(wa, a1.y, acc[3]);
        acc[4] = fmaf(wa, a2.x, acc[4]);
        acc[5] = fmaf(wa, a2.y, acc[5]);
        acc[6] = fmaf(wa, a3.x, acc[6]);
        acc[7] = fmaf(wa, a3.y, acc[7]);
    }

#pragma unroll
    for (int s = 2; s < 32; s <<= 1) {
#pragma unroll
        for (int i = 0; i < 8; i++)
            acc[i] += __shfl_xor_sync(0xffffffffu, acc[i], s);
    }

    if (node < N && lane < 2) {
        if (WRITE_H) {
            __align__(16) __half2 h[4];
#pragma unroll
            for (int j = 0; j < 4; j++) h[j] = __floats2half2_rn(acc[2 * j], acc[2 * j + 1]);
            *reinterpret_cast<int4*>(outh + (size_t)node * 16 + fl * 8) =
                *reinterpret_cast<const int4*>(h);
        } else {
            float4* fp = reinterpret_cast<float4*>(outf + (size_t)node * 16 + fl * 8);
            fp[0] = make_float4(acc[0], acc[1], acc[2], acc[3]);
            fp[1] = make_float4(acc[4], acc[5], acc[6], acc[7]);
        }
    }
}

// ---- layer-3 combine: x2 fp32 + th3 fp16 + s2f fp32, 256 nodes/block -------
__global__ void __launch_bounds__(256) k_combine3(
    const float* __restrict__ x2, const float* __restrict__ su3,
    const __half* __restrict__ t1h, const float* __restrict__ s2,
    const float* __restrict__ W, const float* __restrict__ b,
    float* __restrict__ out, int N) {
    constexpr int FI = 16, FO = 64;
    __shared__ float sW[3 * FI * FO];
    __shared__ float sb[FO], sm[FI], srv[FI];
    for (int i = threadIdx.x; i < FI * FO; i += blockDim.x) {
        float w0 = W[i], w1 = W[FI * FO + i], w2 = W[2 * FI * FO + i];
        sW[i] = w0 - w2;
        sW[FI * FO + i] = w1;
        sW[2 * FI * FO + i] = 2.f * w2;
    }
    if ((int)threadIdx.x < FO) sb[threadIdx.x] = b[threadIdx.x];
    if ((int)threadIdx.x < FI) {
        float invn = 1.f / (float)N;
        float mm = su3[threadIdx.x] * invn;
        float var = su3[FI + threadIdx.x] * invn - mm * mm;
        if (var < 0.f) var = 0.f;
        sm[threadIdx.x] = mm;
        srv[threadIdx.x] = rsqrtf(var + 1e-5f);
    }
    __syncthreads();
    int node = blockIdx.x * blockDim.x + threadIdx.x;
    if (node >= N) return;

    float acc[FO];
#pragma unroll
    for (int j = 0; j < FO; j++) acc[j] = sb[j];

    const float4* xp = reinterpret_cast<const float4*>(x2 + (size_t)node * FI);
    const __half2* tp = reinterpret_cast<const __half2*>(t1h + (size_t)node * FI);
    const float4* sp = reinterpret_cast<const float4*>(s2 + (size_t)node * FI);

#pragma unroll 1
    for (int q = 0; q < 4; q++) {
        float4 xf = xp[q];
        float2 tf0 = __half22float2(tp[q * 2]);
        float2 tf1 = __half22float2(tp[q * 2 + 1]);
        float4 sf = sp[q];
        float xv[4] = {xf.x, xf.y, xf.z, xf.w};
        float tv[4] = {tf0.x, tf0.y, tf1.x, tf1.y};
        float sv[4] = {sf.x, sf.y, sf.z, sf.w};
#pragma unroll
        for (int h = 0; h < 4; h++) {
            int k = q * 4 + h;
            float xn = (xv[h] - sm[k]) * srv[k];
#pragma unroll
            for (int j = 0; j < FO; j++) {
                float w0 = sW[k * FO + j];
                float w1 = sW[FI * FO + k * FO + j];
                float w2 = sW[2 * FI * FO + k * FO + j];
                acc[j] = fmaf(xn, w0, fmaf(tv[h], w1, fmaf(sv[h], w2, acc[j])));
            }
        }
    }
    float4* op = reinterpret_cast<float4*>(out + (size_t)node * FO);
#pragma unroll
    for (int j = 0; j < FO / 4; j++)
        op[j] = make_float4(fmaxf(acc[4 * j], 0.f), fmaxf(acc[4 * j + 1], 0.f),
                            fmaxf(acc[4 * j + 2], 0.f), fmaxf(acc[4 * j + 3], 0.f));
}

// ---- layer4 projections; stats from su4 ------------------------------------
__global__ void k_uqr(const float* __restrict__ x3, const float* __restrict__ su4,
                      const float* __restrict__ W, int N) {
    __shared__ float wu[64], wq[64], wr[64], sm[64], srv[64];
    int t = threadIdx.x;
    if (t < 64) {
        float w0 = W[t], w1 = W[64 + t], w2 = W[128 + t];
        wu[t] = w0 - w2; wq[t] = w1; wr[t] = w2;
        float invn = 1.f / (float)N;
        float mm = su4[t] * invn;
        float var = su4[64 + t] * invn - mm * mm;
        if (var < 0.f) var = 0.f;
        sm[t] = mm;
        srv[t] = rsqrtf(var + 1e-5f);
    }
    __syncthreads();
    int n = blockIdx.x * blockDim.x + t;
    if (n >= N) return;
    float u = 0.f, q = 0.f, r = 0.f;
#pragma unroll
    for (int k = 0; k < 64; k++) {
        float xin = (x3[(size_t)n * 64 + k] - sm[k]) * srv[k];
        u = fmaf(xin, wu[k], u);
        q = fmaf(xin, wq[k], q);
        r = fmaf(xin, wr[k], r);
    }
    g_u[n] = u;
    *reinterpret_cast<float2*>(&g_qr[n * 2]) = make_float2(q, r);
}

// ---- node MLP: xs(85) -> 40 -> 16 -> 1; x4 computed inline -----------------
__global__ void __launch_bounds__(128) k_nodemlp(
    const float* __restrict__ l1W, const float* __restrict__ l1b,
    const float* __restrict__ l2W, const float* __restrict__ l2b,
    const float* __restrict__ l3W, const float* __restrict__ l3b,
    const float* __restrict__ c4b,
    float* __restrict__ xo, int N) {
    __shared__ float sW1[85 * 40], sb1[40], sW2[40 * 16], sb2[16], sW3[16], sb3[1], sb4[1];
    for (int i = threadIdx.x; i < 85 * 40; i += blockDim.x) sW1[i] = l1W[i];
    for (int i = threadIdx.x; i < 40 * 16; i += blockDim.x) sW2[i] = l2W[i];
    if (threadIdx.x < 40) sb1[threadIdx.x] = l1b[threadIdx.x];
    if (threadIdx.x < 16) { sb2[threadIdx.x] = l2b[threadIdx.x]; sW3[threadIdx.x] = l3W[threadIdx.x]; }
    if (threadIdx.x == 0) { sb3[0] = l3b[0]; sb4[0] = c4b[0]; }
    __syncthreads();

    int base = blockIdx.x * blockDim.x * 2 + threadIdx.x;
    int n0 = base, n1 = base + blockDim.x;
    bool v0ok = n0 < N, v1ok = n1 < N;

    float h1[2][40];
#pragma unroll
    for (int j = 0; j < 40; j++) { h1[0][j] = sb1[j]; h1[1][j] = sb1[j]; }

#pragma unroll 1
    for (int k = 0; k < 4; k++) {
        float a = v0ok ? g_x1[n0 * 4 + k] : 0.f;
        float bb = v1ok ? g_x1[n1 * 4 + k] : 0.f;
#pragma unroll
        for (int j = 0; j < 40; j++) {
            float w = sW1[k * 40 + j];
            h1[0][j] = fmaf(a, w, h1[0][j]);
            h1[1][j] = fmaf(bb, w, h1[1][j]);
        }
    }
#pragma unroll 1
    for (int k = 0; k < 16; k++) {
        float a = v0ok ? g_x2[n0 * 16 + k] : 0.f;
        float bb = v1ok ? g_x2[n1 * 16 + k] : 0.f;
#pragma unroll
        for (int j = 0; j < 40; j++) {
            float w = sW1[(4 + k) * 40 + j];
            h1[0][j] = fmaf(a, w, h1[0][j]);
            h1[1][j] = fmaf(bb, w, h1[1][j]);
        }
    }
#pragma unroll 1
    for (int k = 0; k < 64; k++) {
        float a = v0ok ? g_x3[n0 * 64 + k] : 0.f;
        float bb = v1ok ? g_x3[n1 * 64 + k] : 0.f;
#pragma unroll
        for (int j = 0; j < 40; j++) {
            float w = sW1[(20 + k) * 40 + j];
            h1[0][j] = fmaf(a, w, h1[0][j]);
            h1[1][j] = fmaf(bb, w, h1[1][j]);
        }
    }
    {   // x4 = relu(u + Tq + 2*t + cheb4_b)
        float a = v0ok ? fmaxf(g_u[n0] + g_tqs[n0 * 2] + 2.f * g_t[n0] + sb4[0], 0.f) : 0.f;
        float bb = v1ok ? fmaxf(g_u[n1] + g_tqs[n1 * 2] + 2.f * g_t[n1] + sb4[0], 0.f) : 0.f;
#pragma unroll
        for (int j = 0; j < 40; j++) {
            float w = sW1[84 * 40 + j];
            h1[0][j] = fmaf(a, w, h1[0][j]);
            h1[1][j] = fmaf(bb, w, h1[1][j]);
        }
    }
#pragma unroll
    for (int j = 0; j < 40; j++) { h1[0][j] = fmaxf(h1[0][j], 0.f); h1[1][j] = fmaxf(h1[1][j], 0.f); }

    float h2[2][16];
#pragma unroll
    for (int j = 0; j < 16; j++) { h2[0][j] = sb2[j]; h2[1][j] = sb2[j]; }
#pragma unroll
    for (int k = 0; k < 40; k++) {
        float a = h1[0][k], bb = h1[1][k];
#pragma unroll
        for (int j = 0; j < 16; j++) {
            float w = sW2[k * 16 + j];
            h2[0][j] = fmaf(a, w, h2[0][j]);
            h2[1][j] = fmaf(bb, w, h2[1][j]);
        }
    }
    float o0 = sb3[0], o1 = sb3[0];
#pragma unroll
    for (int k = 0; k < 16; k++) {
        float w = sW3[k];
        o0 = fmaf(fmaxf(h2[0][k], 0.f), w, o0);
        o1 = fmaf(fmaxf(h2[1][k], 0.f), w, o1);
    }
    if (v0ok) xo[n0] = fmaxf(o0, 0.f);
    if (v1ok) xo[n1] = fmaxf(o1, 0.f);
}

// ---- edge MLPs (4 edges per thread) ----------------------------------------
__device__ __forceinline__ float edge_mlp(float s, float d, float a,
                                          const float* __restrict__ w1,
                                          const float* __restrict__ b1,
                                          const float* __restrict__ g,
                                          const float* __restrict__ be,
                                          const float* __restrict__ w2,
                                          const float* __restrict__ b2) {
    float h0 = fmaf(s, __ldg(&w1[0]), fmaf(d, __ldg(&w1[2]), fmaf(a, __ldg(&w1[4]), __ldg(&b1[0]))));
    float h1 = fmaf(s, __ldg(&w1[1]), fmaf(d, __ldg(&w1[3]), fmaf(a, __ldg(&w1[5]), __ldg(&b1[1]))));
    h0 = fmaxf(h0, 0.f);
    h1 = fmaxf(h1, 0.f);
    float m = 0.5f * (h0 + h1);
    float d0 = h0 - m, d1 = h1 - m;
    float var = 0.5f * (d0 * d0 + d1 * d1);
    float rs = rsqrtf(var + 1e-5f);
    h0 = fmaf(d0 * rs, __ldg(&g[0]), 0.f) + __ldg(&be[0]);
    h1 = fmaf(d1 * rs, __ldg(&g[1]), 0.f) + __ldg(&be[1]);
    return fmaf(h0, __ldg(&w2[0]), fmaf(h1, __ldg(&w2[1]), __ldg(&b2[0])));
}

__global__ void k_edge(const int* __restrict__ ei, const float* __restrict__ ea,
                       const float* __restrict__ xo,
                       const float* __restrict__ w11, const float* __restrict__ b11,
                       const float* __restrict__ g1, const float* __restrict__ be1,
                       const float* __restrict__ w12, const float* __restrict__ b12,
                       const float* __restrict__ w21, const float* __restrict__ b21,
                       const float* __restrict__ g2, const float* __restrict__ be2,
                       const float* __restrict__ w22, const float* __restrict__ b22,
                       float* __restrict__ out, int E) {
    int e0 = (blockIdx.x * blockDim.x + threadIdx.x) * 4;
    if (e0 >= E) return;
    if (e0 + 3 < E && (E & 3) == 0) {
        int4 rr = *reinterpret_cast<const int4*>(ei + e0);
        int4 cc = *reinterpret_cast<const int4*>(ei + E + e0);
        float4 aa = *reinterpret_cast<const float4*>(ea + e0);
        int rA[4] = {rr.x, rr.y, rr.z, rr.w};
        int cA[4] = {cc.x, cc.y, cc.z, cc.w};
        float aA[4] = {aa.x, aa.y, aa.z, aa.w};
        float oA[4];
#pragma unroll
        for (int i = 0; i < 4; i++) {
            float s = __ldg(&xo[rA[i]]);
            float d = __ldg(&xo[cA[i]]);
            float o1 = fmaxf(edge_mlp(s, d, aA[i], w11, b11, g1, be1, w12, b12), 0.f);
            oA[i] = fmaxf(edge_mlp(s, d, o1, w21, b21, g2, be2, w22, b22), 0.f);
        }
        *reinterpret_cast<float4*>(out + e0) = make_float4(oA[0], oA[1], oA[2], oA[3]);
    } else {
        int eend = (e0 + 4 < E) ? (e0 + 4) : E;
        for (int e = e0; e < eend; e++) {
            int r = ei[e];
            int c = ei[E + e];
            float s = __ldg(&xo[r]);
            float d = __ldg(&xo[c]);
            float a = ea[e];
            float o1 = fmaxf(edge_mlp(s, d, a, w11, b11, g1, be1, w12, b12), 0.f);
            out[e] = fmaxf(edge_mlp(s, d, o1, w21, b21, g2, be2, w22, b22), 0.f);
        }
    }
}

// ---------------------------------------------------------------------------
extern "C" void kernel_launch(void* const* d_in, const int* in_sizes, int n_in,
                              void* d_out, int out_size) {
    (void)n_in; (void)out_size;
    const float* x   = (const float*)d_in[0];
    const int*   ei  = (const int*)d_in[1];
    const float* ea  = (const float*)d_in[2];
    const float* c1W = (const float*)d_in[3];  const float* c1b = (const float*)d_in[4];
    const float* c2W = (const float*)d_in[5];  const float* c2b = (const float*)d_in[6];
    const float* c3W = (const float*)d_in[7];  const float* c3b = (const float*)d_in[8];
    const float* c4W = (const float*)d_in[9];  const float* c4b = (const float*)d_in[10];
    const float* l1W = (const float*)d_in[11]; const float* l1b = (const float*)d_in[12];
    const float* l2W = (const float*)d_in[13]; const float* l2b = (const float*)d_in[14];
    const float* l3W = (const float*)d_in[15]; const float* l3b = (const float*)d_in[16];
    const float* e1w1 = (const float*)d_in[17]; const float* e1b1 = (const float*)d_in[18];
    const float* e1g  = (const float*)d_in[19]; const float* e1be = (const float*)d_in[20];
    const float* e1w2 = (const float*)d_in[21]; const float* e1b2 = (const float*)d_in[22];
    const float* e2w1 = (const float*)d_in[23]; const float* e2b1 = (const float*)d_in[24];
    const float* e2g  = (const float*)d_in[25]; const float* e2be = (const float*)d_in[26];
    const float* e2w2 = (const float*)d_in[27]; const float* e2b2 = (const float*)d_in[28];

    int N = in_sizes[0];
    int E = in_sizes[1] / 2;
    float* out = (float*)d_out;
    float* xo = out;
    float* eaout = out + N;

    void* p;
    float *sums, *x1, *x2, *x3, *tx1, *s2f, *qr, *tqs, *tt;
    __half *xn3, *th3;
    cudaGetSymbolAddress(&p, g_sums); sums = (float*)p;
    cudaGetSymbolAddress(&p, g_x1);   x1   = (float*)p;
    cudaGetSymbolAddress(&p, g_x2);   x2   = (float*)p;
    cudaGetSymbolAddress(&p, g_x3);   x3   = (float*)p;
    cudaGetSymbolAddress(&p, g_tx1);  tx1  = (float*)p;
    cudaGetSymbolAddress(&p, g_s2f);  s2f  = (float*)p;
    cudaGetSymbolAddress(&p, g_qr);   qr   = (float*)p;
    cudaGetSymbolAddress(&p, g_tqs);  tqs  = (float*)p;
    cudaGetSymbolAddress(&p, g_t);    tt   = (float*)p;
    cudaGetSymbolAddress(&p, g_xn3);  xn3  = (__half*)p;
    cudaGetSymbolAddress(&p, g_th3);  th3  = (__half*)p;

    int gN = (N + 255) / 256;
    int NB = (N + 511) / 512;
    int gE2 = (E / 2 + 255) / 256 + 1;
    int gE4 = (E / 4 + 255) / 256 + 1;

    auto spmm_grid = [](int n, int group) {
        int npw = 32 / group;
        long long warps = (n + npw - 1) / npw;
        return (int)((warps * 32 + 255) / 256);
    };
    int gWarp = (int)(((long long)N * 32 + 255) / 256);   // 1 warp per node

    float* su1 = sums + 0;
    float* su2 = sums + 2;
    float* su3 = sums + 10;
    float* su4 = sums + 42;

    // ---- preprocessing ----
    k_zero<<<gN, 256>>>(N);
    k_count<<<gE2, 256>>>(ei, ea, E);
    k_scanA<<<NB, 512>>>(N);
    k_scanC<<<gN, 256>>>(x, N, E, su1);
    k_scatter<<<gE2, 256>>>(ei, ea, E);

    // ---- layer 1: 1 -> 4 ----
    k_spmm<1, 1, 4, true><<<spmm_grid(N, 4), 256>>>(x, su1, tx1, N, 1, 1);
    k_fuse1<<<(N * 4 + 255) / 256, 256>>>(x, su1, tx1, c1W, c1b, x1, su2, N);

    // ---- layer 2: 4 -> 16 ----
    k_spmm<4, 4, 16, true><<<spmm_grid(N, 16), 256>>>(x1, su2, tx1, N, 4, 4);
    k_fuse2<<<(N + 15) / 16, 256>>>(x1, su2, tx1, c2W, c2b, x2, su3, N);

    // ---- layer 3: 16 -> 64 (fp16 gathers; combine reads x2 f32 / th3 h / s2f f32) ----
    k_prenorm16<<<(N * 8 + 255) / 256, 256>>>(x2, su3, xn3, N * 8, N);
    k_spmm16h<true ><<<gWarp, 256>>>(xn3, th3, nullptr, N);  // th3 (fp16 only)
    k_spmm16h<false><<<gWarp, 256>>>(th3, nullptr, s2f, N);  // s2f (fp32 only)
    k_combine3<<<gN, 256>>>(x2, su3, th3, s2f, c3W, c3b, x3, N);

    // ---- layer 4: 64 -> 1 via spmm/matmul commute ----
    k_reduce<64><<<512, 256>>>(x3, su4, N);
    k_uqr<<<gN, 256>>>(x3, su4, c4W, N);
    k_spmm<2, 2, 8, false><<<spmm_grid(N, 8), 256>>>(qr, nullptr, tqs, N, 2, 2);      // (Tq, s)
    k_spmm<1, 1, 4, false><<<spmm_grid(N, 4), 256>>>(tqs + 1, nullptr, tt, N, 2, 1);  // t = spmm(s)

    // ---- node MLP and edge MLPs ----
    k_nodemlp<<<gN, 128>>>(l1W, l1b, l2W, l2b, l3W, l3b, c4b, xo, N);
    k_edge<<<gE4, 256>>>(ei, ea, xo,
                        e1w1, e1b1, e1g, e1be, e1w2, e1b2,
                        e2w1, e2b1, e2g, e2be, e2w2, e2b2,
                        eaout, E);
}